// round 14
// baseline (speedup 1.0000x reference)
#include <cuda_runtime.h>
#include <cuda_bf16.h>
#include <cstdint>
#include <cstddef>
#include <cstring>

#define NN 100000
#define NE 1600000
#define SCAN_B 512
#define SCAN_NB ((NN + SCAN_B - 1) / SCAN_B)   // 196
#define NSM 152

// ---------------- scratch (static device globals; no allocs allowed) ----------------
__device__ int   g_degi[NN];
__device__ float g_dinv[NN];
__device__ int   g_csr[NE];
__device__ int   g_rowptr[NN + 1];
__device__ int   g_cursor[NN];
__device__ int   g_bsum[256];
__device__ __align__(16) float g_agg1[(size_t)NN * 40];
__device__ __align__(16) float g_h1[(size_t)NN * 64];
__device__ __align__(16) float g_agg2[(size_t)NN * 64];
__device__ __align__(16) float g_z[(size_t)NN * 4];

__device__ __forceinline__ void red_add_f4(float* addr, float a, float b, float c, float d) {
    asm volatile("red.global.add.v4.f32 [%0], {%1,%2,%3,%4};"
                 :: "l"(addr), "f"(a), "f"(b), "f"(c), "f"(d) : "memory");
}
__device__ __forceinline__ void red_add_f(float* addr, float v) {
    asm volatile("red.global.add.f32 [%0], %1;" :: "l"(addr), "f"(v) : "memory");
}

__device__ __forceinline__ bool ei_is64(const int* __restrict__ ei32) {
    bool is64 = true;
#pragma unroll
    for (int q = 1; q < 16; q += 2) is64 = is64 && (ei32[q] == 0);
    return is64;
}

// ==================== CSR build ====================
__global__ void k_zero0(float* __restrict__ out) {
    int i = blockIdx.x * blockDim.x + threadIdx.x;
    if (i < NN) g_degi[i] = 0;
    if (i < NN * 4) g_z[i] = 0.f;
    if (i < NN * 3) out[i] = 0.f;
}

__global__ void k_edges(const int* __restrict__ ei32) {
    bool is64 = ei_is64(ei32);
    int e = blockIdx.x * blockDim.x + threadIdx.x;
    if (e >= NE) return;
    int d;
    if (is64) {
        const long long* ei64 = reinterpret_cast<const long long*>(ei32);
        d = (int)ei64[NE + e];
    } else {
        d = ei32[NE + e];
    }
    atomicAdd(&g_degi[d], 1);
}

__global__ void k_scan1() {
    __shared__ int sh[SCAN_B];
    int i = blockIdx.x * SCAN_B + threadIdx.x;
    int v = (i < NN) ? g_degi[i] : 0;
    sh[threadIdx.x] = v;
    __syncthreads();
    for (int off = 1; off < SCAN_B; off <<= 1) {
        int t = (threadIdx.x >= off) ? sh[threadIdx.x - off] : 0;
        __syncthreads();
        sh[threadIdx.x] += t;
        __syncthreads();
    }
    if (i < NN) {
        g_rowptr[i] = sh[threadIdx.x] - v;
        g_dinv[i] = (v > 0) ? (1.f / (float)v) : 0.f;
    }
    if (threadIdx.x == SCAN_B - 1) g_bsum[blockIdx.x] = sh[threadIdx.x];
}

__global__ void k_scanf() {
    __shared__ int ssum[8];
    int tid = threadIdx.x;
    int nb = (blockIdx.x * 256) / SCAN_B;
    int part = 0;
    for (int b = tid; b < nb; b += 256) part += g_bsum[b];
#pragma unroll
    for (int o = 16; o; o >>= 1) part += __shfl_down_sync(0xFFFFFFFFu, part, o);
    if ((tid & 31) == 0) ssum[tid >> 5] = part;
    __syncthreads();
    int off = ssum[0] + ssum[1] + ssum[2] + ssum[3]
            + ssum[4] + ssum[5] + ssum[6] + ssum[7];
    int i = blockIdx.x * 256 + tid;
    if (i >= NN) return;
    int rp = g_rowptr[i] + off;
    g_rowptr[i] = rp;
    g_cursor[i] = rp;
    if (i == 0) g_rowptr[NN] = NE;
}

__global__ void k_fill(const int* __restrict__ ei32) {
    bool is64 = ei_is64(ei32);
    int e = blockIdx.x * blockDim.x + threadIdx.x;
    if (e >= NE) return;
    int s, d;
    if (is64) {
        const long long* ei64 = reinterpret_cast<const long long*>(ei32);
        s = (int)ei64[e];
        d = (int)ei64[NE + e];
    } else {
        s = ei32[e];
        d = ei32[NE + e];
    }
    int pos = atomicAdd(&g_cursor[d], 1);
    g_csr[pos] = s;
}

// ==================== CSR gather (fp32, unroll x4, index-pipelined) ====================
// Next quad's csr loads issued BEFORE current quad's feature loads -> idx latency
// overlaps feat latency instead of serializing with it.
template <int F4>
__global__ void k_gather(const float* __restrict__ feat, float* __restrict__ agg) {
    int t = blockIdx.x * blockDim.x + threadIdx.x;
    if (t >= NN * F4) return;
    int n = t / F4;
    int c = t - n * F4;
    int beg = g_rowptr[n], end = g_rowptr[n + 1];
    const float4* f = reinterpret_cast<const float4*>(feat);
    float4 a0 = make_float4(0.f, 0.f, 0.f, 0.f), a1 = a0, a2 = a0, a3 = a0;
    int i = beg;
    if (i + 4 <= end) {
        int s0 = g_csr[i], s1 = g_csr[i + 1], s2 = g_csr[i + 2], s3 = g_csr[i + 3];
        i += 4;
        for (; i + 4 <= end; i += 4) {
            int t0 = g_csr[i], t1 = g_csr[i + 1], t2 = g_csr[i + 2], t3 = g_csr[i + 3];
            float4 v0 = f[(size_t)s0 * F4 + c];
            float4 v1 = f[(size_t)s1 * F4 + c];
            float4 v2 = f[(size_t)s2 * F4 + c];
            float4 v3 = f[(size_t)s3 * F4 + c];
            a0.x += v0.x; a0.y += v0.y; a0.z += v0.z; a0.w += v0.w;
            a1.x += v1.x; a1.y += v1.y; a1.z += v1.z; a1.w += v1.w;
            a2.x += v2.x; a2.y += v2.y; a2.z += v2.z; a2.w += v2.w;
            a3.x += v3.x; a3.y += v3.y; a3.z += v3.z; a3.w += v3.w;
            s0 = t0; s1 = t1; s2 = t2; s3 = t3;
        }
        float4 v0 = f[(size_t)s0 * F4 + c];
        float4 v1 = f[(size_t)s1 * F4 + c];
        float4 v2 = f[(size_t)s2 * F4 + c];
        float4 v3 = f[(size_t)s3 * F4 + c];
        a0.x += v0.x; a0.y += v0.y; a0.z += v0.z; a0.w += v0.w;
        a1.x += v1.x; a1.y += v1.y; a1.z += v1.z; a1.w += v1.w;
        a2.x += v2.x; a2.y += v2.y; a2.z += v2.z; a2.w += v2.w;
        a3.x += v3.x; a3.y += v3.y; a3.z += v3.z; a3.w += v3.w;
    }
    for (; i < end; i++) {
        float4 v = f[(size_t)g_csr[i] * F4 + c];
        a0.x += v.x; a0.y += v.y; a0.z += v.z; a0.w += v.w;
    }
    float di = g_dinv[n];
    float4 acc;
    acc.x = ((a0.x + a1.x) + (a2.x + a3.x)) * di;
    acc.y = ((a0.y + a1.y) + (a2.y + a3.y)) * di;
    acc.z = ((a0.z + a1.z) + (a2.z + a3.z)) * di;
    acc.w = ((a0.w + a1.w) + (a2.w + a3.w)) * di;
    reinterpret_cast<float4*>(agg)[t] = acc;
}

// ==================== HMMA helpers ====================
__device__ __forceinline__ void mma_bf16(float* c, uint32_t a0, uint32_t a1,
                                         uint32_t a2, uint32_t a3,
                                         uint32_t b0, uint32_t b1) {
    asm volatile(
        "mma.sync.aligned.m16n8k16.row.col.f32.bf16.bf16.f32 "
        "{%0,%1,%2,%3}, {%4,%5,%6,%7}, {%8,%9}, {%0,%1,%2,%3};"
        : "+f"(c[0]), "+f"(c[1]), "+f"(c[2]), "+f"(c[3])
        : "r"(a0), "r"(a1), "r"(a2), "r"(a3), "r"(b0), "r"(b1));
}

__device__ __forceinline__ uint32_t pack_bf(float a, float b) {
    __nv_bfloat162 t = __floats2bfloat162_rn(a, b);
    uint32_t u;
    memcpy(&u, &t, 4);
    return u;
}

__device__ __forceinline__ void store_hilo(char* pHi, char* pLo, float4 v) {
    float hx = __bfloat162float(__float2bfloat16_rn(v.x));
    float hy = __bfloat162float(__float2bfloat16_rn(v.y));
    float hz = __bfloat162float(__float2bfloat16_rn(v.z));
    float hw = __bfloat162float(__float2bfloat16_rn(v.w));
    *reinterpret_cast<uint2*>(pHi) = make_uint2(pack_bf(hx, hy), pack_bf(hz, hw));
    *reinterpret_cast<uint2*>(pLo) =
        make_uint2(pack_bf(v.x - hx, v.y - hy), pack_bf(v.z - hz, v.w - hw));
}

// ==================== fused SAGE layer via mma.sync (bf16 hi/lo split) ====================
template <int K, int NOUTB, bool FUSE3>
__global__ void __launch_bounds__(256) k_layer_mma(
        const float* __restrict__ in, const float* __restrict__ agg,
        const float* __restrict__ Wl, const float* __restrict__ bias,
        const float* __restrict__ Wr, float* __restrict__ out, int NOUT,
        const float* __restrict__ W4l, const float* __restrict__ W4r,
        float* __restrict__ out3) {
    constexpr int Kc = 2 * K;
    constexpr int KSTEPS = Kc / 16;
    constexpr int K4 = Kc / 4;
    constexpr int SA = Kc + 8;
    constexpr int SAB = SA * 2;
    constexpr int NT = (NOUTB / 2) / 8;
    constexpr int NTILES = (NN + 127) / 128;
    constexpr int OFF_W4 = 256;
    constexpr int OFF_AH = 2560;
    constexpr int OFF_AL = OFF_AH + 128 * SAB;
    constexpr int OFF_BH = OFF_AL + 128 * SAB;
    constexpr int OFF_BL = OFF_BH + NOUTB * SAB;

    extern __shared__ char smem[];
    float* sbias = reinterpret_cast<float*>(smem);
    float* sW4l = reinterpret_cast<float*>(smem + OFF_W4);
    float* sW4r = sW4l + 256;
    char* sAh = smem + OFF_AH;
    char* sAl = smem + OFF_AL;
    char* sBh = smem + OFF_BH;
    char* sBl = smem + OFF_BL;

    int tid = threadIdx.x;
    int wid = tid >> 5, lane = tid & 31;
    int g = lane >> 2, tg = lane & 3;
    int mwarp = (wid & 3) * 32;
    int nwarp = (wid >> 2) * (NOUTB / 2);
    int coloff = blockIdx.y * NOUTB;

    if (tid < NOUTB) sbias[tid] = bias[coloff + tid];
    if (FUSE3 && tid < 192) {
        int lcol = tid / 3, m = tid - lcol * 3;
        sW4l[lcol * 4 + m] = W4l[m * 128 + coloff + lcol];
        sW4r[lcol * 4 + m] = W4r[m * 128 + coloff + lcol];
    }
    for (int idx = tid; idx < NOUTB * K4; idx += 256) {
        int row = idx / K4, k4 = idx - row * K4;
        int k = k4 * 4;
        int grow = coloff + row;
        float4 v = (k < K)
            ? *reinterpret_cast<const float4*>(Wl + (size_t)grow * K + k)
            : *reinterpret_cast<const float4*>(Wr + (size_t)grow * K + (k - K));
        store_hilo(sBh + row * SAB + k * 2, sBl + row * SAB + k * 2, v);
    }
    __syncthreads();

    for (int tile = blockIdx.x; tile < NTILES; tile += gridDim.x) {
        int r0 = tile * 128;
        for (int idx = tid; idx < 128 * K4; idx += 256) {
            int row = idx / K4, k4 = idx - row * K4;
            int k = k4 * 4;
            int gr = r0 + row;
            float4 v = make_float4(0.f, 0.f, 0.f, 0.f);
            if (gr < NN) {
                v = (k < K)
                    ? *reinterpret_cast<const float4*>(agg + (size_t)gr * K + k)
                    : *reinterpret_cast<const float4*>(in + (size_t)gr * K + (k - K));
            }
            store_hilo(sAh + row * SAB + k * 2, sAl + row * SAB + k * 2, v);
        }
        __syncthreads();

        float C[2][NT][4];
#pragma unroll
        for (int mt = 0; mt < 2; mt++)
#pragma unroll
            for (int nt = 0; nt < NT; nt++)
#pragma unroll
                for (int q = 0; q < 4; q++) C[mt][nt][q] = 0.f;

#pragma unroll
        for (int ks = 0; ks < KSTEPS; ks++) {
            int kb = ks * 16;
            uint32_t Ah[2][4], Al[2][4];
#pragma unroll
            for (int mt = 0; mt < 2; mt++) {
                const char* pa = sAh + (mwarp + mt * 16 + g) * SAB + kb * 2 + tg * 4;
                const char* pl = sAl + (mwarp + mt * 16 + g) * SAB + kb * 2 + tg * 4;
                Ah[mt][0] = *(const uint32_t*)(pa);
                Ah[mt][1] = *(const uint32_t*)(pa + 8 * SAB);
                Ah[mt][2] = *(const uint32_t*)(pa + 16);
                Ah[mt][3] = *(const uint32_t*)(pa + 8 * SAB + 16);
                Al[mt][0] = *(const uint32_t*)(pl);
                Al[mt][1] = *(const uint32_t*)(pl + 8 * SAB);
                Al[mt][2] = *(const uint32_t*)(pl + 16);
                Al[mt][3] = *(const uint32_t*)(pl + 8 * SAB + 16);
            }
            uint32_t Bh[NT][2], Bl[NT][2];
#pragma unroll
            for (int nt = 0; nt < NT; nt++) {
                const char* pb = sBh + (nwarp + nt * 8 + g) * SAB + kb * 2 + tg * 4;
                const char* pq = sBl + (nwarp + nt * 8 + g) * SAB + kb * 2 + tg * 4;
                Bh[nt][0] = *(const uint32_t*)(pb);
                Bh[nt][1] = *(const uint32_t*)(pb + 16);
                Bl[nt][0] = *(const uint32_t*)(pq);
                Bl[nt][1] = *(const uint32_t*)(pq + 16);
            }
#pragma unroll
            for (int mt = 0; mt < 2; mt++)
#pragma unroll
                for (int nt = 0; nt < NT; nt++) {
                    mma_bf16(C[mt][nt], Ah[mt][0], Ah[mt][1], Ah[mt][2], Ah[mt][3],
                             Bh[nt][0], Bh[nt][1]);
                    mma_bf16(C[mt][nt], Al[mt][0], Al[mt][1], Al[mt][2], Al[mt][3],
                             Bh[nt][0], Bh[nt][1]);
                    mma_bf16(C[mt][nt], Ah[mt][0], Ah[mt][1], Ah[mt][2], Ah[mt][3],
                             Bl[nt][0], Bl[nt][1]);
                }
        }
        __syncthreads();

        if (!FUSE3) {
#pragma unroll
            for (int mt = 0; mt < 2; mt++) {
                int rowA = r0 + mwarp + mt * 16 + g;
                int rowB = rowA + 8;
#pragma unroll
                for (int nt = 0; nt < NT; nt++) {
                    int lcol = nwarp + nt * 8 + tg * 2;
                    int col = coloff + lcol;
                    float bx = sbias[lcol], by = sbias[lcol + 1];
                    if (rowA < NN) {
                        float2 o;
                        o.x = fmaxf(C[mt][nt][0] + bx, 0.f);
                        o.y = fmaxf(C[mt][nt][1] + by, 0.f);
                        *reinterpret_cast<float2*>(&out[(size_t)rowA * NOUT + col]) = o;
                    }
                    if (rowB < NN) {
                        float2 o;
                        o.x = fmaxf(C[mt][nt][2] + bx, 0.f);
                        o.y = fmaxf(C[mt][nt][3] + by, 0.f);
                        *reinterpret_cast<float2*>(&out[(size_t)rowB * NOUT + col]) = o;
                    }
                }
            }
        } else {
#pragma unroll
            for (int mt = 0; mt < 2; mt++) {
                int rowA = r0 + mwarp + mt * 16 + g;
                int rowB = rowA + 8;
                float zA[3] = {0.f, 0.f, 0.f}, rA[3] = {0.f, 0.f, 0.f};
                float zB[3] = {0.f, 0.f, 0.f}, rB[3] = {0.f, 0.f, 0.f};
#pragma unroll
                for (int nt = 0; nt < NT; nt++) {
                    int lcol = nwarp + nt * 8 + tg * 2;
                    float bx = sbias[lcol], by = sbias[lcol + 1];
                    float oxA = fmaxf(C[mt][nt][0] + bx, 0.f);
                    float oyA = fmaxf(C[mt][nt][1] + by, 0.f);
                    float oxB = fmaxf(C[mt][nt][2] + bx, 0.f);
                    float oyB = fmaxf(C[mt][nt][3] + by, 0.f);
#pragma unroll
                    for (int m = 0; m < 3; m++) {
                        float wl0 = sW4l[lcol * 4 + m], wl1 = sW4l[(lcol + 1) * 4 + m];
                        float wr0 = sW4r[lcol * 4 + m], wr1 = sW4r[(lcol + 1) * 4 + m];
                        zA[m] += oxA * wl0 + oyA * wl1;
                        rA[m] += oxA * wr0 + oyA * wr1;
                        zB[m] += oxB * wl0 + oyB * wl1;
                        rB[m] += oxB * wr0 + oyB * wr1;
                    }
                }
#pragma unroll
                for (int m = 0; m < 3; m++) {
                    zA[m] += __shfl_xor_sync(0xFFFFFFFFu, zA[m], 1);
                    zA[m] += __shfl_xor_sync(0xFFFFFFFFu, zA[m], 2);
                    rA[m] += __shfl_xor_sync(0xFFFFFFFFu, rA[m], 1);
                    rA[m] += __shfl_xor_sync(0xFFFFFFFFu, rA[m], 2);
                    zB[m] += __shfl_xor_sync(0xFFFFFFFFu, zB[m], 1);
                    zB[m] += __shfl_xor_sync(0xFFFFFFFFu, zB[m], 2);
                    rB[m] += __shfl_xor_sync(0xFFFFFFFFu, rB[m], 1);
                    rB[m] += __shfl_xor_sync(0xFFFFFFFFu, rB[m], 2);
                }
                if (tg == 0) {
                    if (rowA < NN) {
                        red_add_f4(&g_z[(size_t)rowA * 4], zA[0], zA[1], zA[2], 0.f);
                        red_add_f(&out3[(size_t)rowA * 3 + 0], rA[0]);
                        red_add_f(&out3[(size_t)rowA * 3 + 1], rA[1]);
                        red_add_f(&out3[(size_t)rowA * 3 + 2], rA[2]);
                    }
                    if (rowB < NN) {
                        red_add_f4(&g_z[(size_t)rowB * 4], zB[0], zB[1], zB[2], 0.f);
                        red_add_f(&out3[(size_t)rowB * 3 + 0], rB[0]);
                        red_add_f(&out3[(size_t)rowB * 3 + 1], rB[1]);
                        red_add_f(&out3[(size_t)rowB * 3 + 2], rB[2]);
                    }
                }
            }
        }
    }
}

// ==================== final: out += b4 + dinv * sum z[neighbors] (pipelined) ====================
__global__ void k_gather3(const float* __restrict__ b4, float* __restrict__ out) {
    int n = blockIdx.x * blockDim.x + threadIdx.x;
    if (n >= NN) return;
    int beg = g_rowptr[n], end = g_rowptr[n + 1];
    const float4* z4 = reinterpret_cast<const float4*>(g_z);
    float4 a0 = make_float4(0.f, 0.f, 0.f, 0.f), a1 = a0, a2 = a0, a3 = a0;
    int i = beg;
    if (i + 4 <= end) {
        int s0 = g_csr[i], s1 = g_csr[i + 1], s2 = g_csr[i + 2], s3 = g_csr[i + 3];
        i += 4;
        for (; i + 4 <= end; i += 4) {
            int t0 = g_csr[i], t1 = g_csr[i + 1], t2 = g_csr[i + 2], t3 = g_csr[i + 3];
            float4 v0 = z4[s0], v1 = z4[s1], v2 = z4[s2], v3 = z4[s3];
            a0.x += v0.x; a0.y += v0.y; a0.z += v0.z;
            a1.x += v1.x; a1.y += v1.y; a1.z += v1.z;
            a2.x += v2.x; a2.y += v2.y; a2.z += v2.z;
            a3.x += v3.x; a3.y += v3.y; a3.z += v3.z;
            s0 = t0; s1 = t1; s2 = t2; s3 = t3;
        }
        float4 v0 = z4[s0], v1 = z4[s1], v2 = z4[s2], v3 = z4[s3];
        a0.x += v0.x; a0.y += v0.y; a0.z += v0.z;
        a1.x += v1.x; a1.y += v1.y; a1.z += v1.z;
        a2.x += v2.x; a2.y += v2.y; a2.z += v2.z;
        a3.x += v3.x; a3.y += v3.y; a3.z += v3.z;
    }
    for (; i < end; i++) {
        float4 v = z4[g_csr[i]];
        a0.x += v.x; a0.y += v.y; a0.z += v.z;
    }
    float di = g_dinv[n];
    out[(size_t)n * 3 + 0] += ((a0.x + a1.x) + (a2.x + a3.x)) * di + b4[0];
    out[(size_t)n * 3 + 1] += ((a0.y + a1.y) + (a2.y + a3.y)) * di + b4[1];
    out[(size_t)n * 3 + 2] += ((a0.z + a1.z) + (a2.z + a3.z)) * di + b4[2];
}

// ==================== launch ====================
extern "C" void kernel_launch(void* const* d_in, const int* in_sizes, int n_in,
                              void* d_out, int out_size) {
    (void)in_sizes; (void)n_in; (void)out_size;
    const float* x   = (const float*)d_in[0];
    const int*   ei  = (const int*)d_in[1];
    const float* W1l = (const float*)d_in[2];
    const float* b1  = (const float*)d_in[3];
    const float* W1r = (const float*)d_in[4];
    const float* W2l = (const float*)d_in[5];
    const float* b2  = (const float*)d_in[6];
    const float* W2r = (const float*)d_in[7];
    const float* W4l = (const float*)d_in[8];
    const float* b4  = (const float*)d_in[9];
    const float* W4r = (const float*)d_in[10];
    float* out = (float*)d_out;

    void *p_agg1, *p_agg2, *p_h1;
    cudaGetSymbolAddress(&p_agg1, g_agg1);
    cudaGetSymbolAddress(&p_agg2, g_agg2);
    cudaGetSymbolAddress(&p_h1, g_h1);

    int smem1 = 2560 + 2 * 128 * (88 * 2) + 2 * 64 * (88 * 2);    // 70144  -> 3 blocks/SM
    int smem2 = 2560 + 2 * 128 * (136 * 2) + 2 * 64 * (136 * 2);  // 107008 -> 2 blocks/SM
    cudaFuncSetAttribute((const void*)k_layer_mma<40, 64, false>,
                         cudaFuncAttributeMaxDynamicSharedMemorySize, smem1);
    cudaFuncSetAttribute((const void*)k_layer_mma<64, 64, true>,
                         cudaFuncAttributeMaxDynamicSharedMemorySize, smem2);

    // CSR build (+ zero red-targets)
    k_zero0<<<(NN * 4 + 255) / 256, 256>>>(out);
    k_edges<<<(NE + 255) / 256, 256>>>(ei);
    k_scan1<<<SCAN_NB, SCAN_B>>>();
    k_scanf<<<(NN + 255) / 256, 256>>>();
    k_fill<<<(NE + 255) / 256, 256>>>(ei);

    // layer 1: gather x (pipelined), fused linear -> h1 [N,64]
    k_gather<10><<<(NN * 10 + 255) / 256, 256>>>(x, (float*)p_agg1);
    k_layer_mma<40, 64, false><<<dim3(3 * NSM, 1), 256, smem1>>>(
        x, (const float*)p_agg1, W1l, b1, W1r, (float*)p_h1, 64,
        nullptr, nullptr, nullptr);

    // layer 2 (+fused layer-3): gather h1 (pipelined), linear, RED epilogue into g_z/out
    k_gather<16><<<(NN * 16 + 255) / 256, 256>>>((const float*)p_h1, (float*)p_agg2);
    k_layer_mma<64, 64, true><<<dim3(NSM, 2), 256, smem2>>>(
        (const float*)p_h1, (const float*)p_agg2, W2l, b2, W2r, nullptr, 128,
        W4l, W4r, out);

    // final: out += b4 + mean-aggregated z
    k_gather3<<<(NN + 255) / 256, 256>>>(b4, out);
}

// round 15
// speedup vs baseline: 1.0429x; 1.0429x over previous
#include <cuda_runtime.h>
#include <cuda_bf16.h>
#include <cstdint>
#include <cstddef>
#include <cstring>

#define NN 100000
#define NE 1600000
#define SCAN_B 512
#define SCAN_NB ((NN + SCAN_B - 1) / SCAN_B)   // 196
#define NSM 152

// ---------------- scratch (static device globals; no allocs allowed) ----------------
__device__ int   g_degi[NN];
__device__ float g_dinv[NN];
__device__ int   g_csr[NE];
__device__ int   g_rowptr[NN + 1];
__device__ int   g_cursor[NN];
__device__ int   g_bsum[256];
__device__ __align__(16) float g_agg1[(size_t)NN * 40];
__device__ __align__(16) float g_h1[(size_t)NN * 64];
__device__ __align__(16) float g_agg2[(size_t)NN * 64];
__device__ __align__(16) float g_z[(size_t)NN * 4];

__device__ __forceinline__ void red_add_f4(float* addr, float a, float b, float c, float d) {
    asm volatile("red.global.add.v4.f32 [%0], {%1,%2,%3,%4};"
                 :: "l"(addr), "f"(a), "f"(b), "f"(c), "f"(d) : "memory");
}
__device__ __forceinline__ void red_add_f(float* addr, float v) {
    asm volatile("red.global.add.f32 [%0], %1;" :: "l"(addr), "f"(v) : "memory");
}

__device__ __forceinline__ bool ei_is64(const int* __restrict__ ei32) {
    bool is64 = true;
#pragma unroll
    for (int q = 1; q < 16; q += 2) is64 = is64 && (ei32[q] == 0);
    return is64;
}

// ==================== CSR build ====================
// slim: only the degree histogram target
__global__ void k_zero0() {
    int i = blockIdx.x * blockDim.x + threadIdx.x;
    if (i < NN) g_degi[i] = 0;
}

__global__ void k_edges(const int* __restrict__ ei32) {
    bool is64 = ei_is64(ei32);
    int e = blockIdx.x * blockDim.x + threadIdx.x;
    if (e >= NE) return;
    int d;
    if (is64) {
        const long long* ei64 = reinterpret_cast<const long long*>(ei32);
        d = (int)ei64[NE + e];
    } else {
        d = ei32[NE + e];
    }
    atomicAdd(&g_degi[d], 1);
}

__global__ void k_scan1() {
    __shared__ int sh[SCAN_B];
    int i = blockIdx.x * SCAN_B + threadIdx.x;
    int v = (i < NN) ? g_degi[i] : 0;
    sh[threadIdx.x] = v;
    __syncthreads();
    for (int off = 1; off < SCAN_B; off <<= 1) {
        int t = (threadIdx.x >= off) ? sh[threadIdx.x - off] : 0;
        __syncthreads();
        sh[threadIdx.x] += t;
        __syncthreads();
    }
    if (i < NN) {
        g_rowptr[i] = sh[threadIdx.x] - v;
        g_dinv[i] = (v > 0) ? (1.f / (float)v) : 0.f;
    }
    if (threadIdx.x == SCAN_B - 1) g_bsum[blockIdx.x] = sh[threadIdx.x];
}

// finalize rowptr/cursor + zero the RED targets (g_z, out) using the same threads
__global__ void k_scanf(float* __restrict__ out) {
    __shared__ int ssum[8];
    int tid = threadIdx.x;
    int nb = (blockIdx.x * 256) / SCAN_B;
    int part = 0;
    for (int b = tid; b < nb; b += 256) part += g_bsum[b];
#pragma unroll
    for (int o = 16; o; o >>= 1) part += __shfl_down_sync(0xFFFFFFFFu, part, o);
    if ((tid & 31) == 0) ssum[tid >> 5] = part;
    __syncthreads();
    int off = ssum[0] + ssum[1] + ssum[2] + ssum[3]
            + ssum[4] + ssum[5] + ssum[6] + ssum[7];
    int i = blockIdx.x * 256 + tid;
    if (i >= NN) return;
    int rp = g_rowptr[i] + off;
    g_rowptr[i] = rp;
    g_cursor[i] = rp;
    reinterpret_cast<float4*>(g_z)[i] = make_float4(0.f, 0.f, 0.f, 0.f);
    out[(size_t)i * 3 + 0] = 0.f;
    out[(size_t)i * 3 + 1] = 0.f;
    out[(size_t)i * 3 + 2] = 0.f;
    if (i == 0) g_rowptr[NN] = NE;
}

__global__ void k_fill(const int* __restrict__ ei32) {
    bool is64 = ei_is64(ei32);
    int e = blockIdx.x * blockDim.x + threadIdx.x;
    if (e >= NE) return;
    int s, d;
    if (is64) {
        const long long* ei64 = reinterpret_cast<const long long*>(ei32);
        s = (int)ei64[e];
        d = (int)ei64[NE + e];
    } else {
        s = ei32[e];
        d = ei32[NE + e];
    }
    int pos = atomicAdd(&g_cursor[d], 1);
    g_csr[pos] = s;
}

// ==================== CSR gather (fp32, unroll x4 — the measured equilibrium; R13 exact) ====================
template <int F4>
__global__ void k_gather(const float* __restrict__ feat, float* __restrict__ agg) {
    int t = blockIdx.x * blockDim.x + threadIdx.x;
    if (t >= NN * F4) return;
    int n = t / F4;
    int c = t - n * F4;
    int beg = g_rowptr[n], end = g_rowptr[n + 1];
    const float4* f = reinterpret_cast<const float4*>(feat);
    float4 a0 = make_float4(0.f, 0.f, 0.f, 0.f), a1 = a0, a2 = a0, a3 = a0;
    int i = beg;
    for (; i + 4 <= end; i += 4) {
        int s0 = g_csr[i], s1 = g_csr[i + 1], s2 = g_csr[i + 2], s3 = g_csr[i + 3];
        float4 v0 = f[(size_t)s0 * F4 + c];
        float4 v1 = f[(size_t)s1 * F4 + c];
        float4 v2 = f[(size_t)s2 * F4 + c];
        float4 v3 = f[(size_t)s3 * F4 + c];
        a0.x += v0.x; a0.y += v0.y; a0.z += v0.z; a0.w += v0.w;
        a1.x += v1.x; a1.y += v1.y; a1.z += v1.z; a1.w += v1.w;
        a2.x += v2.x; a2.y += v2.y; a2.z += v2.z; a2.w += v2.w;
        a3.x += v3.x; a3.y += v3.y; a3.z += v3.z; a3.w += v3.w;
    }
    for (; i < end; i++) {
        float4 v = f[(size_t)g_csr[i] * F4 + c];
        a0.x += v.x; a0.y += v.y; a0.z += v.z; a0.w += v.w;
    }
    float di = g_dinv[n];
    float4 acc;
    acc.x = ((a0.x + a1.x) + (a2.x + a3.x)) * di;
    acc.y = ((a0.y + a1.y) + (a2.y + a3.y)) * di;
    acc.z = ((a0.z + a1.z) + (a2.z + a3.z)) * di;
    acc.w = ((a0.w + a1.w) + (a2.w + a3.w)) * di;
    reinterpret_cast<float4*>(agg)[t] = acc;
}

// ==================== HMMA helpers ====================
__device__ __forceinline__ void mma_bf16(float* c, uint32_t a0, uint32_t a1,
                                         uint32_t a2, uint32_t a3,
                                         uint32_t b0, uint32_t b1) {
    asm volatile(
        "mma.sync.aligned.m16n8k16.row.col.f32.bf16.bf16.f32 "
        "{%0,%1,%2,%3}, {%4,%5,%6,%7}, {%8,%9}, {%0,%1,%2,%3};"
        : "+f"(c[0]), "+f"(c[1]), "+f"(c[2]), "+f"(c[3])
        : "r"(a0), "r"(a1), "r"(a2), "r"(a3), "r"(b0), "r"(b1));
}

__device__ __forceinline__ uint32_t pack_bf(float a, float b) {
    __nv_bfloat162 t = __floats2bfloat162_rn(a, b);
    uint32_t u;
    memcpy(&u, &t, 4);
    return u;
}

__device__ __forceinline__ void store_hilo(char* pHi, char* pLo, float4 v) {
    float hx = __bfloat162float(__float2bfloat16_rn(v.x));
    float hy = __bfloat162float(__float2bfloat16_rn(v.y));
    float hz = __bfloat162float(__float2bfloat16_rn(v.z));
    float hw = __bfloat162float(__float2bfloat16_rn(v.w));
    *reinterpret_cast<uint2*>(pHi) = make_uint2(pack_bf(hx, hy), pack_bf(hz, hw));
    *reinterpret_cast<uint2*>(pLo) =
        make_uint2(pack_bf(v.x - hx, v.y - hy), pack_bf(v.z - hz, v.w - hw));
}

// ==================== fused SAGE layer via mma.sync (bf16 hi/lo split) ====================
template <int K, int NOUTB, bool FUSE3>
__global__ void __launch_bounds__(256) k_layer_mma(
        const float* __restrict__ in, const float* __restrict__ agg,
        const float* __restrict__ Wl, const float* __restrict__ bias,
        const float* __restrict__ Wr, float* __restrict__ out, int NOUT,
        const float* __restrict__ W4l, const float* __restrict__ W4r,
        float* __restrict__ out3) {
    constexpr int Kc = 2 * K;
    constexpr int KSTEPS = Kc / 16;
    constexpr int K4 = Kc / 4;
    constexpr int SA = Kc + 8;
    constexpr int SAB = SA * 2;
    constexpr int NT = (NOUTB / 2) / 8;
    constexpr int NTILES = (NN + 127) / 128;
    constexpr int OFF_W4 = 256;
    constexpr int OFF_AH = 2560;
    constexpr int OFF_AL = OFF_AH + 128 * SAB;
    constexpr int OFF_BH = OFF_AL + 128 * SAB;
    constexpr int OFF_BL = OFF_BH + NOUTB * SAB;

    extern __shared__ char smem[];
    float* sbias = reinterpret_cast<float*>(smem);
    float* sW4l = reinterpret_cast<float*>(smem + OFF_W4);
    float* sW4r = sW4l + 256;
    char* sAh = smem + OFF_AH;
    char* sAl = smem + OFF_AL;
    char* sBh = smem + OFF_BH;
    char* sBl = smem + OFF_BL;

    int tid = threadIdx.x;
    int wid = tid >> 5, lane = tid & 31;
    int g = lane >> 2, tg = lane & 3;
    int mwarp = (wid & 3) * 32;
    int nwarp = (wid >> 2) * (NOUTB / 2);
    int coloff = blockIdx.y * NOUTB;

    if (tid < NOUTB) sbias[tid] = bias[coloff + tid];
    if (FUSE3 && tid < 192) {
        int lcol = tid / 3, m = tid - lcol * 3;
        sW4l[lcol * 4 + m] = W4l[m * 128 + coloff + lcol];
        sW4r[lcol * 4 + m] = W4r[m * 128 + coloff + lcol];
    }
    for (int idx = tid; idx < NOUTB * K4; idx += 256) {
        int row = idx / K4, k4 = idx - row * K4;
        int k = k4 * 4;
        int grow = coloff + row;
        float4 v = (k < K)
            ? *reinterpret_cast<const float4*>(Wl + (size_t)grow * K + k)
            : *reinterpret_cast<const float4*>(Wr + (size_t)grow * K + (k - K));
        store_hilo(sBh + row * SAB + k * 2, sBl + row * SAB + k * 2, v);
    }
    __syncthreads();

    for (int tile = blockIdx.x; tile < NTILES; tile += gridDim.x) {
        int r0 = tile * 128;
        for (int idx = tid; idx < 128 * K4; idx += 256) {
            int row = idx / K4, k4 = idx - row * K4;
            int k = k4 * 4;
            int gr = r0 + row;
            float4 v = make_float4(0.f, 0.f, 0.f, 0.f);
            if (gr < NN) {
                v = (k < K)
                    ? *reinterpret_cast<const float4*>(agg + (size_t)gr * K + k)
                    : *reinterpret_cast<const float4*>(in + (size_t)gr * K + (k - K));
            }
            store_hilo(sAh + row * SAB + k * 2, sAl + row * SAB + k * 2, v);
        }
        __syncthreads();

        float C[2][NT][4];
#pragma unroll
        for (int mt = 0; mt < 2; mt++)
#pragma unroll
            for (int nt = 0; nt < NT; nt++)
#pragma unroll
                for (int q = 0; q < 4; q++) C[mt][nt][q] = 0.f;

#pragma unroll
        for (int ks = 0; ks < KSTEPS; ks++) {
            int kb = ks * 16;
            uint32_t Ah[2][4], Al[2][4];
#pragma unroll
            for (int mt = 0; mt < 2; mt++) {
                const char* pa = sAh + (mwarp + mt * 16 + g) * SAB + kb * 2 + tg * 4;
                const char* pl = sAl + (mwarp + mt * 16 + g) * SAB + kb * 2 + tg * 4;
                Ah[mt][0] = *(const uint32_t*)(pa);
                Ah[mt][1] = *(const uint32_t*)(pa + 8 * SAB);
                Ah[mt][2] = *(const uint32_t*)(pa + 16);
                Ah[mt][3] = *(const uint32_t*)(pa + 8 * SAB + 16);
                Al[mt][0] = *(const uint32_t*)(pl);
                Al[mt][1] = *(const uint32_t*)(pl + 8 * SAB);
                Al[mt][2] = *(const uint32_t*)(pl + 16);
                Al[mt][3] = *(const uint32_t*)(pl + 8 * SAB + 16);
            }
            uint32_t Bh[NT][2], Bl[NT][2];
#pragma unroll
            for (int nt = 0; nt < NT; nt++) {
                const char* pb = sBh + (nwarp + nt * 8 + g) * SAB + kb * 2 + tg * 4;
                const char* pq = sBl + (nwarp + nt * 8 + g) * SAB + kb * 2 + tg * 4;
                Bh[nt][0] = *(const uint32_t*)(pb);
                Bh[nt][1] = *(const uint32_t*)(pb + 16);
                Bl[nt][0] = *(const uint32_t*)(pq);
                Bl[nt][1] = *(const uint32_t*)(pq + 16);
            }
#pragma unroll
            for (int mt = 0; mt < 2; mt++)
#pragma unroll
                for (int nt = 0; nt < NT; nt++) {
                    mma_bf16(C[mt][nt], Ah[mt][0], Ah[mt][1], Ah[mt][2], Ah[mt][3],
                             Bh[nt][0], Bh[nt][1]);
                    mma_bf16(C[mt][nt], Al[mt][0], Al[mt][1], Al[mt][2], Al[mt][3],
                             Bh[nt][0], Bh[nt][1]);
                    mma_bf16(C[mt][nt], Ah[mt][0], Ah[mt][1], Ah[mt][2], Ah[mt][3],
                             Bl[nt][0], Bl[nt][1]);
                }
        }
        __syncthreads();

        if (!FUSE3) {
#pragma unroll
            for (int mt = 0; mt < 2; mt++) {
                int rowA = r0 + mwarp + mt * 16 + g;
                int rowB = rowA + 8;
#pragma unroll
                for (int nt = 0; nt < NT; nt++) {
                    int lcol = nwarp + nt * 8 + tg * 2;
                    int col = coloff + lcol;
                    float bx = sbias[lcol], by = sbias[lcol + 1];
                    if (rowA < NN) {
                        float2 o;
                        o.x = fmaxf(C[mt][nt][0] + bx, 0.f);
                        o.y = fmaxf(C[mt][nt][1] + by, 0.f);
                        *reinterpret_cast<float2*>(&out[(size_t)rowA * NOUT + col]) = o;
                    }
                    if (rowB < NN) {
                        float2 o;
                        o.x = fmaxf(C[mt][nt][2] + bx, 0.f);
                        o.y = fmaxf(C[mt][nt][3] + by, 0.f);
                        *reinterpret_cast<float2*>(&out[(size_t)rowB * NOUT + col]) = o;
                    }
                }
            }
        } else {
#pragma unroll
            for (int mt = 0; mt < 2; mt++) {
                int rowA = r0 + mwarp + mt * 16 + g;
                int rowB = rowA + 8;
                float zA[3] = {0.f, 0.f, 0.f}, rA[3] = {0.f, 0.f, 0.f};
                float zB[3] = {0.f, 0.f, 0.f}, rB[3] = {0.f, 0.f, 0.f};
#pragma unroll
                for (int nt = 0; nt < NT; nt++) {
                    int lcol = nwarp + nt * 8 + tg * 2;
                    float bx = sbias[lcol], by = sbias[lcol + 1];
                    float oxA = fmaxf(C[mt][nt][0] + bx, 0.f);
                    float oyA = fmaxf(C[mt][nt][1] + by, 0.f);
                    float oxB = fmaxf(C[mt][nt][2] + bx, 0.f);
                    float oyB = fmaxf(C[mt][nt][3] + by, 0.f);
#pragma unroll
                    for (int m = 0; m < 3; m++) {
                        float wl0 = sW4l[lcol * 4 + m], wl1 = sW4l[(lcol + 1) * 4 + m];
                        float wr0 = sW4r[lcol * 4 + m], wr1 = sW4r[(lcol + 1) * 4 + m];
                        zA[m] += oxA * wl0 + oyA * wl1;
                        rA[m] += oxA * wr0 + oyA * wr1;
                        zB[m] += oxB * wl0 + oyB * wl1;
                        rB[m] += oxB * wr0 + oyB * wr1;
                    }
                }
#pragma unroll
                for (int m = 0; m < 3; m++) {
                    zA[m] += __shfl_xor_sync(0xFFFFFFFFu, zA[m], 1);
                    zA[m] += __shfl_xor_sync(0xFFFFFFFFu, zA[m], 2);
                    rA[m] += __shfl_xor_sync(0xFFFFFFFFu, rA[m], 1);
                    rA[m] += __shfl_xor_sync(0xFFFFFFFFu, rA[m], 2);
                    zB[m] += __shfl_xor_sync(0xFFFFFFFFu, zB[m], 1);
                    zB[m] += __shfl_xor_sync(0xFFFFFFFFu, zB[m], 2);
                    rB[m] += __shfl_xor_sync(0xFFFFFFFFu, rB[m], 1);
                    rB[m] += __shfl_xor_sync(0xFFFFFFFFu, rB[m], 2);
                }
                if (tg == 0) {
                    if (rowA < NN) {
                        red_add_f4(&g_z[(size_t)rowA * 4], zA[0], zA[1], zA[2], 0.f);
                        red_add_f(&out3[(size_t)rowA * 3 + 0], rA[0]);
                        red_add_f(&out3[(size_t)rowA * 3 + 1], rA[1]);
                        red_add_f(&out3[(size_t)rowA * 3 + 2], rA[2]);
                    }
                    if (rowB < NN) {
                        red_add_f4(&g_z[(size_t)rowB * 4], zB[0], zB[1], zB[2], 0.f);
                        red_add_f(&out3[(size_t)rowB * 3 + 0], rB[0]);
                        red_add_f(&out3[(size_t)rowB * 3 + 1], rB[1]);
                        red_add_f(&out3[(size_t)rowB * 3 + 2], rB[2]);
                    }
                }
            }
        }
    }
}

// ==================== final: out += b4 + dinv * sum z[neighbors] (R13 exact) ====================
__global__ void k_gather3(const float* __restrict__ b4, float* __restrict__ out) {
    int n = blockIdx.x * blockDim.x + threadIdx.x;
    if (n >= NN) return;
    int beg = g_rowptr[n], end = g_rowptr[n + 1];
    const float4* z4 = reinterpret_cast<const float4*>(g_z);
    float4 a0 = make_float4(0.f, 0.f, 0.f, 0.f), a1 = a0, a2 = a0, a3 = a0;
    int i = beg;
    for (; i + 4 <= end; i += 4) {
        float4 v0 = z4[g_csr[i]];
        float4 v1 = z4[g_csr[i + 1]];
        float4 v2 = z4[g_csr[i + 2]];
        float4 v3 = z4[g_csr[i + 3]];
        a0.x += v0.x; a0.y += v0.y; a0.z += v0.z;
        a1.x += v1.x; a1.y += v1.y; a1.z += v1.z;
        a2.x += v2.x; a2.y += v2.y; a2.z += v2.z;
        a3.x += v3.x; a3.y += v3.y; a3.z += v3.z;
    }
    for (; i < end; i++) {
        float4 v = z4[g_csr[i]];
        a0.x += v.x; a0.y += v.y; a0.z += v.z;
    }
    float di = g_dinv[n];
    out[(size_t)n * 3 + 0] += ((a0.x + a1.x) + (a2.x + a3.x)) * di + b4[0];
    out[(size_t)n * 3 + 1] += ((a0.y + a1.y) + (a2.y + a3.y)) * di + b4[1];
    out[(size_t)n * 3 + 2] += ((a0.z + a1.z) + (a2.z + a3.z)) * di + b4[2];
}

// ==================== launch ====================
extern "C" void kernel_launch(void* const* d_in, const int* in_sizes, int n_in,
                              void* d_out, int out_size) {
    (void)in_sizes; (void)n_in; (void)out_size;
    const float* x   = (const float*)d_in[0];
    const int*   ei  = (const int*)d_in[1];
    const float* W1l = (const float*)d_in[2];
    const float* b1  = (const float*)d_in[3];
    const float* W1r = (const float*)d_in[4];
    const float* W2l = (const float*)d_in[5];
    const float* b2  = (const float*)d_in[6];
    const float* W2r = (const float*)d_in[7];
    const float* W4l = (const float*)d_in[8];
    const float* b4  = (const float*)d_in[9];
    const float* W4r = (const float*)d_in[10];
    float* out = (float*)d_out;

    void *p_agg1, *p_agg2, *p_h1;
    cudaGetSymbolAddress(&p_agg1, g_agg1);
    cudaGetSymbolAddress(&p_agg2, g_agg2);
    cudaGetSymbolAddress(&p_h1, g_h1);

    int smem1 = 2560 + 2 * 128 * (88 * 2) + 2 * 64 * (88 * 2);    // 70144  -> 3 blocks/SM
    int smem2 = 2560 + 2 * 128 * (136 * 2) + 2 * 64 * (136 * 2);  // 107008 -> 2 blocks/SM
    cudaFuncSetAttribute((const void*)k_layer_mma<40, 64, false>,
                         cudaFuncAttributeMaxDynamicSharedMemorySize, smem1);
    cudaFuncSetAttribute((const void*)k_layer_mma<64, 64, true>,
                         cudaFuncAttributeMaxDynamicSharedMemorySize, smem2);

    // CSR build; RED-target zeroing folded into k_scanf
    k_zero0<<<(NN + 255) / 256, 256>>>();
    k_edges<<<(NE + 255) / 256, 256>>>(ei);
    k_scan1<<<SCAN_NB, SCAN_B>>>();
    k_scanf<<<(NN + 255) / 256, 256>>>(out);
    k_fill<<<(NE + 255) / 256, 256>>>(ei);

    // layer 1: gather x (R13-exact equilibrium), fused linear -> h1 [N,64]
    k_gather<10><<<(NN * 10 + 255) / 256, 256>>>(x, (float*)p_agg1);
    k_layer_mma<40, 64, false><<<dim3(3 * NSM, 1), 256, smem1>>>(
        x, (const float*)p_agg1, W1l, b1, W1r, (float*)p_h1, 64,
        nullptr, nullptr, nullptr);

    // layer 2 (+fused layer-3): gather h1, linear, RED epilogue into g_z/out
    k_gather<16><<<(NN * 16 + 255) / 256, 256>>>((const float*)p_h1, (float*)p_agg2);
    k_layer_mma<64, 64, true><<<dim3(NSM, 2), 256, smem2>>>(
        (const float*)p_h1, (const float*)p_agg2, W2l, b2, W2r, nullptr, 128,
        W4l, W4r, out);

    // final: out += b4 + mean-aggregated z
    k_gather3<<<(NN + 255) / 256, 256>>>(b4, out);
}